// round 15
// baseline (speedup 1.0000x reference)
#include <cuda_runtime.h>
#include <cuda_fp16.h>
#include <cstdint>

// ---------------- problem constants ----------------
#define NMAX   50048      // padded node capacity
#define EMAX   800000
#define GMAX   64
#define HD     128        // hidden dim (H*D)
#define PW     256        // q|skip packed row width for layer 1

// ---------------- static scratch (no allocs allowed) ----------------
__device__ float    g_P[(size_t)NMAX * PW];    // layer1 packed q|s (fp32)
__device__ __half2  g_KV[(size_t)NMAX * 128];  // layer1 per node: k | v (fp16)
__device__ float    g_H1[(size_t)NMAX * HD];   // layer1 output (post relu)
__device__ float    g_A[(size_t)NMAX * 8];     // layer0 compact attn results
__device__ float    g_M0[18];                  // layer0 3x3 bilinear forms (2 heads)
__device__ float    g_cq0[6];                  // layer0 q.We coefficient 3-vectors
__device__ float    g_C[9 * 128];              // layer0 expansion matrix (Z @ C = H0)
__device__ uint32_t g_WH[4 * 128 * 64];        // pre-split fp16-hi weights [sec][col][kpair]
__device__ uint32_t g_WL[4 * 128 * 64];        // pre-split fp16-lo weights
__device__ int      g_degcnt[2 * NMAX];        // [0,NMAX): degree, [NMAX,2N): scatter cursor
__device__ int      g_rowptr[NMAX + 1];
__device__ int2     g_edge[EMAX];              // packed (src, attr-bits)
__device__ int      g_gstart[GMAX + 1];
__device__ float    g_poolp[GMAX * 8 * HD];    // partial pool sums

// ---------------- CSR build ----------------
__global__ void hist_kernel(const int* __restrict__ dst, int E) {
    int i = blockIdx.x * blockDim.x + threadIdx.x;
    if (i < E) atomicAdd(&g_degcnt[dst[i]], 1);
}

__global__ void scan_kernel(int N) {
    __shared__ int sums[1024];
    int t = threadIdx.x;
    int chunk = (N + 1023) >> 10;
    chunk = (chunk + 3) & ~3;
    int lo = t * chunk;
    int hi = min(lo + chunk, N);
    int s = 0;
    int i = lo;
    for (; i + 4 <= hi; i += 4) {
        int4 v = *(const int4*)(g_degcnt + i);
        s += v.x + v.y + v.z + v.w;
    }
    for (; i < hi; i++) s += g_degcnt[i];
    sums[t] = s;
    __syncthreads();
    for (int off = 1; off < 1024; off <<= 1) {
        int v = (t >= off) ? sums[t - off] : 0;
        __syncthreads();
        sums[t] += v;
        __syncthreads();
    }
    int run = sums[t] - s;
    for (int j = lo; j < hi; j++) { g_rowptr[j] = run; run += g_degcnt[j]; }
    if (t == 1023) g_rowptr[N] = sums[1023];
}

__global__ void scatter_kernel(const int* __restrict__ src,
                               const int* __restrict__ dst,
                               const float* __restrict__ attr, int E) {
    int i = blockIdx.x * blockDim.x + threadIdx.x;
    if (i >= E) return;
    int d = dst[i];
    int p = g_rowptr[d] + atomicAdd(&g_degcnt[NMAX + d], 1);
    g_edge[p] = make_int2(src[i], __float_as_int(attr[i]));
}

// ---------------- weight pre-split: W[4][128][128] fp32 -> hi/lo half2 kpairs ----------------
__device__ __forceinline__ void split_f16(float x, __half& h, __half& l) {
    h = __float2half_rn(x);
    l = __float2half_rn(x - __half2float(h));
}
__device__ __forceinline__ uint32_t pack2(__half a, __half b) {
    __half2 t = __halves2half2(a, b);
    return *reinterpret_cast<uint32_t*>(&t);
}

__global__ void prepW_kernel(const float* __restrict__ Wq, const float* __restrict__ Wk,
                             const float* __restrict__ Wv, const float* __restrict__ Ws) {
    int t = blockIdx.x * blockDim.x + threadIdx.x;   // 32768 = 4*64*128
    if (t >= 4 * 64 * 128) return;
    int col = t & 127;
    int kp  = (t >> 7) & 63;
    int sec = t >> 13;
    const float* W = (sec == 0) ? Wq : (sec == 1) ? Wk : (sec == 2) ? Wv : Ws;
    float w0 = W[(2 * kp) * 128 + col];
    float w1 = W[(2 * kp + 1) * 128 + col];
    __half h0, l0, h1, l1;
    split_f16(w0, h0, l0);
    split_f16(w1, h1, l1);
    int o = (sec * 128 + col) * 64 + kp;
    g_WH[o] = pack2(h0, h1);
    g_WL[o] = pack2(l0, l1);
}

// ---------------- layer-0 precompute: warp-parallel bilinear forms + C + gstart ----------------
__global__ void prep0_kernel(const float* __restrict__ Wq, const float* __restrict__ bq,
                             const float* __restrict__ Wk, const float* __restrict__ bk,
                             const float* __restrict__ We,
                             const float* __restrict__ Wv, const float* __restrict__ bv,
                             const float* __restrict__ Ws, const float* __restrict__ bs,
                             const int* __restrict__ batch, int N) {
    int tid  = threadIdx.x;
    int w    = tid >> 5, lane = tid & 31;
    if (w < 24) {
        const float* arow; const float* brow;
        if (w < 18) {
            int h = w / 9, rem = w % 9, r = rem / 3, c = rem % 3;
            arow = (r < 2) ? (Wq + r * 128 + h * 64) : (bq + h * 64);
            brow = (c < 2) ? (Wk + c * 128 + h * 64) : (bk + h * 64);
        } else {
            int j = w - 18, h = j / 3, r = j % 3;
            arow = (r < 2) ? (Wq + r * 128 + h * 64) : (bq + h * 64);
            brow = We + h * 64;
        }
        float s = arow[lane] * brow[lane] + arow[lane + 32] * brow[lane + 32];
#pragma unroll
        for (int off = 16; off; off >>= 1) s += __shfl_xor_sync(0xffffffffu, s, off);
        if (lane == 0) {
            if (w < 18) g_M0[w] = s; else g_cq0[w - 18] = s;
        }
    }
    int t2 = tid - 768;
    if (t2 >= 0 && t2 < 128) {
        int h = t2 >> 6;
        g_C[0 * 128 + t2] = (h == 0) ? Wv[t2]        : 0.f;
        g_C[1 * 128 + t2] = (h == 0) ? Wv[128 + t2]  : 0.f;
        g_C[2 * 128 + t2] = (h == 0) ? We[t2]        : 0.f;
        g_C[3 * 128 + t2] = (h == 1) ? Wv[t2]        : 0.f;
        g_C[4 * 128 + t2] = (h == 1) ? Wv[128 + t2]  : 0.f;
        g_C[5 * 128 + t2] = (h == 1) ? We[t2]        : 0.f;
        g_C[6 * 128 + t2] = Ws[t2];
        g_C[7 * 128 + t2] = Ws[128 + t2];
        g_C[8 * 128 + t2] = bv[t2] + bs[t2];
    }
    // graph starts: binary search on sorted batch (threads 896..960)
    int t3 = tid - 896;
    if (t3 >= 0 && t3 <= GMAX) {
        int lo = 0, hi = N;
        while (lo < hi) {
            int mid = (lo + hi) >> 1;
            if (batch[mid] < t3) lo = mid + 1; else hi = mid;
        }
        g_gstart[t3] = lo;
    }
}

// ---------------- layer-0 attention: one THREAD per node ----------------
__global__ void attn0_kernel(const float* __restrict__ x, int N) {
    __shared__ float sM[18], sC[6];
    int t = threadIdx.x;
    if (t < 18) sM[t] = g_M0[t];
    if (t < 6)  sC[t] = g_cq0[t];
    __syncthreads();

    int n = blockIdx.x * blockDim.x + t;
    if (n >= N) return;

    const float2* x2 = (const float2*)x;
    float2 xd = __ldg(x2 + n);

    float w[2][3], cqd[2];
#pragma unroll
    for (int h = 0; h < 2; h++) {
#pragma unroll
        for (int j = 0; j < 3; j++)
            w[h][j] = fmaf(xd.x, sM[h * 9 + j], fmaf(xd.y, sM[h * 9 + 3 + j], sM[h * 9 + 6 + j]));
        cqd[h] = fmaf(xd.x, sC[h * 3], fmaf(xd.y, sC[h * 3 + 1], sC[h * 3 + 2]));
    }

    float m[2]   = {-1e30f, -1e30f};
    float den[2] = {0.f, 0.f};
    float S0[2]  = {0.f, 0.f};
    float S1[2]  = {0.f, 0.f};
    float Sa[2]  = {0.f, 0.f};

    int beg = g_rowptr[n], end = g_rowptr[n + 1];
    float aNxt = 0.f; float2 xsNxt = make_float2(0.f, 0.f);
    if (beg < end) {
        int2 e = __ldg(g_edge + beg);
        aNxt = __int_as_float(e.y);
        xsNxt = __ldg(x2 + e.x);
    }
    for (int i = beg; i < end; i++) {
        float a = aNxt; float2 xs = xsNxt;
        if (i + 1 < end) {
            int2 e = __ldg(g_edge + i + 1);
            aNxt = __int_as_float(e.y);
            xsNxt = __ldg(x2 + e.x);
        }
#pragma unroll
        for (int h = 0; h < 2; h++) {
            float l = fmaf(a, cqd[h],
                      fmaf(xs.x, w[h][0], fmaf(xs.y, w[h][1], w[h][2]))) * 0.125f;
            float nm = fmaxf(m[h], l);
            float sc = __expf(m[h] - nm);
            float ex = __expf(l - nm);
            S0[h] = fmaf(S0[h], sc, ex * xs.x);
            S1[h] = fmaf(S1[h], sc, ex * xs.y);
            Sa[h] = fmaf(Sa[h], sc, ex * a);
            den[h] = fmaf(den[h], sc, ex);
            m[h] = nm;
        }
    }

    float4* A4 = (float4*)g_A;
#pragma unroll
    for (int h = 0; h < 2; h++) {
        float inv = 1.f / (den[h] + 1e-16f);
        A4[(size_t)n * 2 + h] = make_float4(S0[h] * inv, S1[h] * inv, Sa[h] * inv, 0.f);
    }
}

// ---------------- layer-1 projections: fused H0-gen + fp16-split GEMM ----------------
#define PA 10     // A half2 row stride (8 + 2 pad)
#define PB 9      // B half2 col stride (8 + 1 pad)

__device__ __forceinline__ void mma16(float* c, const uint32_t* a, const uint32_t* b) {
    asm volatile(
        "mma.sync.aligned.m16n8k16.row.col.f32.f16.f16.f32 "
        "{%0,%1,%2,%3}, {%4,%5,%6,%7}, {%8,%9}, {%0,%1,%2,%3};"
        : "+f"(c[0]), "+f"(c[1]), "+f"(c[2]), "+f"(c[3])
        : "r"(a[0]), "r"(a[1]), "r"(a[2]), "r"(a[3]), "r"(b[0]), "r"(b[1]));
}

__global__ __launch_bounds__(256, 2) void gemm3_kernel(
    const float* __restrict__ x, int N,
    const float* __restrict__ bq, const float* __restrict__ bk,
    const float* __restrict__ bv, const float* __restrict__ bs) {
    __shared__ uint32_t AsH[128 * PA];
    __shared__ uint32_t AsL[128 * PA];
    __shared__ uint32_t BsH[128 * PB];
    __shared__ uint32_t BsL[128 * PB];
    __shared__ float Cs[9 * 128];    // expansion matrix
    __shared__ float Zs[128 * 10];   // per-row compact features (8 used, pad 10)

    const float* bias;
    int sec = blockIdx.y;
    if (sec == 0)      bias = bq;
    else if (sec == 1) bias = bk;
    else if (sec == 2) bias = bv;
    else               bias = bs;
    bool threePass = (sec == 0 || sec == 3);

    int tid  = threadIdx.x;
    int warp = tid >> 5, lane = tid & 31;
    int g    = lane >> 2, tig = lane & 3;
    int wm   = warp >> 2, wn = warp & 3;         // 2 x 4 warp grid
    int blockM = blockIdx.x * 128;

    // load C + Z once
    for (int i = tid; i < 9 * 128; i += 256) Cs[i] = g_C[i];
    if (tid < 128) {
        int r = blockM + tid;
        float4 A0 = make_float4(0.f, 0.f, 0.f, 0.f);
        float4 A1 = A0;
        float2 xn = make_float2(0.f, 0.f);
        if (r < N) {
            const float4* A4 = (const float4*)g_A;
            A0 = A4[(size_t)r * 2];
            A1 = A4[(size_t)r * 2 + 1];
            xn = ((const float2*)x)[r];
        }
        float* z = &Zs[tid * 10];
        z[0] = A0.x; z[1] = A0.y; z[2] = A0.z;
        z[3] = A1.x; z[4] = A1.y; z[5] = A1.z;
        z[6] = xn.x; z[7] = xn.y;
    }

    float acc[4][4][4];
#pragma unroll
    for (int mt = 0; mt < 4; mt++)
#pragma unroll
        for (int nt = 0; nt < 4; nt++)
#pragma unroll
            for (int c = 0; c < 4; c++) acc[mt][nt][c] = 0.f;

    const uint2* WHg = (const uint2*)(g_WH + (size_t)sec * 128 * 64);
    const uint2* WLg = (const uint2*)(g_WL + (size_t)sec * 128 * 64);

#pragma unroll 1
    for (int kp8 = 0; kp8 < 8; kp8++) {
        int k0 = kp8 * 16;
        __syncthreads();
        // A panel: compute H0[128, k0:k0+16] = relu(Z @ C) on the fly
#pragma unroll
        for (int j = 0; j < 2; j++) {
            int pos = tid + 256 * j;
            int row = pos >> 2;
            int c4  = pos & 3;
            const float* zr = &Zs[row * 10];
            float vals[4];
#pragma unroll
            for (int e = 0; e < 4; e++) {
                int col = k0 + c4 * 4 + e;
                float a = Cs[8 * 128 + col];
#pragma unroll
                for (int i2 = 0; i2 < 8; i2++) a = fmaf(zr[i2], Cs[i2 * 128 + col], a);
                vals[e] = fmaxf(a, 0.f);
            }
            __half hx, lx, hy, ly, hz, lz, hw, lw;
            split_f16(vals[0], hx, lx); split_f16(vals[1], hy, ly);
            split_f16(vals[2], hz, lz); split_f16(vals[3], hw, lw);
            AsH[row * PA + c4 * 2]     = pack2(hx, hy);
            AsH[row * PA + c4 * 2 + 1] = pack2(hz, hw);
            AsL[row * PA + c4 * 2]     = pack2(lx, ly);
            AsL[row * PA + c4 * 2 + 1] = pack2(lz, lw);
        }
        // B panel: copy pre-split halves (layout [col][64 kpairs], panel = 4 uint2)
#pragma unroll
        for (int j = 0; j < 2; j++) {
            int idx = tid * 2 + j;       // 0..511
            int col = idx >> 2;
            int kq  = idx & 3;           // uint2 index within panel
            uint2 h = __ldg(WHg + (col * 32 + kp8 * 4 + kq));
            uint2 l = __ldg(WLg + (col * 32 + kp8 * 4 + kq));
            BsH[col * PB + kq * 2]     = h.x;
            BsH[col * PB + kq * 2 + 1] = h.y;
            BsL[col * PB + kq * 2]     = l.x;
            BsL[col * PB + kq * 2 + 1] = l.y;
        }
        __syncthreads();

        uint32_t bh[4][2], bl[4][2];
#pragma unroll
        for (int nt = 0; nt < 4; nt++) {
            int col = wn * 32 + nt * 8 + g;
            bh[nt][0] = BsH[col * PB + tig];
            bh[nt][1] = BsH[col * PB + tig + 4];
            bl[nt][0] = BsL[col * PB + tig];
            bl[nt][1] = BsL[col * PB + tig + 4];
        }
#pragma unroll
        for (int mt = 0; mt < 4; mt++) {
            int r0 = wm * 64 + mt * 16 + g;
            uint32_t ah[4], al[4];
            ah[0] = AsH[r0 * PA + tig];
            ah[1] = AsH[(r0 + 8) * PA + tig];
            ah[2] = AsH[r0 * PA + tig + 4];
            ah[3] = AsH[(r0 + 8) * PA + tig + 4];
            al[0] = AsL[r0 * PA + tig];
            al[1] = AsL[(r0 + 8) * PA + tig];
            al[2] = AsL[r0 * PA + tig + 4];
            al[3] = AsL[(r0 + 8) * PA + tig + 4];
#pragma unroll
            for (int nt = 0; nt < 4; nt++) {
                mma16(acc[mt][nt], ah, bh[nt]);                  // hi*hi
                mma16(acc[mt][nt], ah, bl[nt]);                  // hi*lo
                if (threePass) mma16(acc[mt][nt], al, bh[nt]);   // lo*hi (q/skip only)
            }
        }
    }

    // epilogue: q -> P cols 0..127; s -> P cols 128..255; k/v -> fp16 KV only
    bool isKV = (sec == 1 || sec == 2);
    int kvOff = (sec == 2) ? 64 : 0;
    int pOff  = (sec == 3) ? 128 : 0;
#pragma unroll
    for (int mt = 0; mt < 4; mt++) {
        int r0 = blockM + wm * 64 + mt * 16 + g;
#pragma unroll
        for (int nt = 0; nt < 4; nt++) {
            int cn = wn * 32 + nt * 8 + tig * 2;
            float b0 = bias[cn], b1 = bias[cn + 1];
            float2 v0 = make_float2(acc[mt][nt][0] + b0, acc[mt][nt][1] + b1);
            float2 v1 = make_float2(acc[mt][nt][2] + b0, acc[mt][nt][3] + b1);
            if (isKV) {
                g_KV[(size_t)r0 * 128 + kvOff + cn / 2]       = __floats2half2_rn(v0.x, v0.y);
                g_KV[(size_t)(r0 + 8) * 128 + kvOff + cn / 2] = __floats2half2_rn(v1.x, v1.y);
            } else {
                *(float2*)(g_P + (size_t)r0 * PW + pOff + cn)       = v0;
                *(float2*)(g_P + (size_t)(r0 + 8) * PW + pOff + cn) = v1;
            }
        }
    }
}

// ---------------- layer-1 edge attention: warp = 1 node, 2 edges/iter ----------------
__device__ __forceinline__ void cvt8(uint4 r, float4& lo, float4& hi) {
    __half2 h0 = *reinterpret_cast<__half2*>(&r.x);
    __half2 h1 = *reinterpret_cast<__half2*>(&r.y);
    __half2 h2 = *reinterpret_cast<__half2*>(&r.z);
    __half2 h3 = *reinterpret_cast<__half2*>(&r.w);
    float2 a = __half22float2(h0), b = __half22float2(h1);
    float2 c = __half22float2(h2), d = __half22float2(h3);
    lo = make_float4(a.x, a.y, b.x, b.y);
    hi = make_float4(c.x, c.y, d.x, d.y);
}

__device__ __forceinline__ float dot8v(float4 a0, float4 a1, float4 b0, float4 b1) {
    return a0.x * b0.x + a0.y * b0.y + a0.z * b0.z + a0.w * b0.w
         + a1.x * b1.x + a1.y * b1.y + a1.z * b1.z + a1.w * b1.w;
}

__global__ void attn_kernel(const float* __restrict__ We, int N) {
    int gt   = blockIdx.x * blockDim.x + threadIdx.x;
    int lane = threadIdx.x & 31;
    int eh   = lane >> 4;          // which edge of the pair this half-warp handles
    int sub  = lane & 15;          // dims sub*8 .. sub*8+7
    int n    = gt >> 5;
    if (n >= N) return;

    const float4* P4 = (const float4*)g_P;
    size_t base = (size_t)n * 64;
    float4 q0 = __ldg(P4 + base + sub * 2);
    float4 q1 = __ldg(P4 + base + sub * 2 + 1);
    float4 w0 = __ldg((const float4*)We + sub * 2);
    float4 w1 = __ldg((const float4*)We + sub * 2 + 1);

    float qWe = dot8v(q0, q1, w0, w1);
    qWe += __shfl_xor_sync(0xffffffffu, qWe, 4);
    qWe += __shfl_xor_sync(0xffffffffu, qWe, 2);
    qWe += __shfl_xor_sync(0xffffffffu, qWe, 1);

    int beg = g_rowptr[n], end = g_rowptr[n + 1];
    int deg = end - beg;
    int npair = (deg + 1) >> 1;

    float4 acc0 = make_float4(0.f, 0.f, 0.f, 0.f);
    float4 acc1 = make_float4(0.f, 0.f, 0.f, 0.f);
    float m = -1e30f, den = 0.f, sa = 0.f;

    for (int i = 0; i < npair; i++) {
        int idx = beg + 2 * i + eh;
        bool v = (idx < end);
        int2 e = __ldg(g_edge + (v ? idx : beg));
        float a = __int_as_float(e.y);
        const uint4* b4 = (const uint4*)(g_KV + (size_t)e.x * 128);
        uint4 kr = __ldg(b4 + sub);
        uint4 vr = __ldg(b4 + 16 + sub);

        float4 k0, k1; cvt8(kr, k0, k1);
        float part = dot8v(q0, q1, k0, k1);
        part += __shfl_xor_sync(0xffffffffu, part, 4);
        part += __shfl_xor_sync(0xffffffffu, part, 2);
        part += __shfl_xor_sync(0xffffffffu, part, 1);
        float l = (part + a * qWe) * 0.125f;

        float nm = v ? fmaxf(m, l) : m;
        float sc = __expf(m - nm);
        float ex = v ? __expf(l - nm) : 0.f;

        float4 v0, v1; cvt8(vr, v0, v1);
        acc0.x = fmaf(acc0.x, sc, ex * v0.x);
        acc0.y = fmaf(acc0.y, sc, ex * v0.y);
        acc0.z = fmaf(acc0.z, sc, ex * v0.z);
        acc0.w = fmaf(acc0.w, sc, ex * v0.w);
        acc1.x = fmaf(acc1.x, sc, ex * v1.x);
        acc1.y = fmaf(acc1.y, sc, ex * v1.y);
        acc1.z = fmaf(acc1.z, sc, ex * v1.z);
        acc1.w = fmaf(acc1.w, sc, ex * v1.w);
        den = fmaf(den, sc, ex);
        sa  = fmaf(sa,  sc, ex * a);
        m = nm;
    }

    // exact merge of the two half-warp states
    float mO = __shfl_xor_sync(0xffffffffu, m, 16);
    float nm = fmaxf(m, mO);
    float eS = __expf(m - nm);
    den *= eS; sa *= eS;
    acc0.x *= eS; acc0.y *= eS; acc0.z *= eS; acc0.w *= eS;
    acc1.x *= eS; acc1.y *= eS; acc1.z *= eS; acc1.w *= eS;
    den += __shfl_xor_sync(0xffffffffu, den, 16);
    sa  += __shfl_xor_sync(0xffffffffu, sa, 16);
    acc0.x += __shfl_xor_sync(0xffffffffu, acc0.x, 16);
    acc0.y += __shfl_xor_sync(0xffffffffu, acc0.y, 16);
    acc0.z += __shfl_xor_sync(0xffffffffu, acc0.z, 16);
    acc0.w += __shfl_xor_sync(0xffffffffu, acc0.w, 16);
    acc1.x += __shfl_xor_sync(0xffffffffu, acc1.x, 16);
    acc1.y += __shfl_xor_sync(0xffffffffu, acc1.y, 16);
    acc1.z += __shfl_xor_sync(0xffffffffu, acc1.z, 16);
    acc1.w += __shfl_xor_sync(0xffffffffu, acc1.w, 16);

    acc0.x = fmaf(sa, w0.x, acc0.x);
    acc0.y = fmaf(sa, w0.y, acc0.y);
    acc0.z = fmaf(sa, w0.z, acc0.z);
    acc0.w = fmaf(sa, w0.w, acc0.w);
    acc1.x = fmaf(sa, w1.x, acc1.x);
    acc1.y = fmaf(sa, w1.y, acc1.y);
    acc1.z = fmaf(sa, w1.z, acc1.z);
    acc1.w = fmaf(sa, w1.w, acc1.w);

    if (eh) return;   // lower half-warp stores the full row
    float inv = 1.f / (den + 1e-16f);
    float4 s0 = __ldg(P4 + base + 32 + sub * 2);
    float4 s1 = __ldg(P4 + base + 32 + sub * 2 + 1);
    float4 o0, o1;
    o0.x = fmaxf(fmaf(acc0.x, inv, s0.x), 0.f);
    o0.y = fmaxf(fmaf(acc0.y, inv, s0.y), 0.f);
    o0.z = fmaxf(fmaf(acc0.z, inv, s0.z), 0.f);
    o0.w = fmaxf(fmaf(acc0.w, inv, s0.w), 0.f);
    o1.x = fmaxf(fmaf(acc1.x, inv, s1.x), 0.f);
    o1.y = fmaxf(fmaf(acc1.y, inv, s1.y), 0.f);
    o1.z = fmaxf(fmaf(acc1.z, inv, s1.z), 0.f);
    o1.w = fmaxf(fmaf(acc1.w, inv, s1.w), 0.f);
    float4* H4 = (float4*)g_H1;
    H4[(size_t)n * 32 + sub * 2]     = o0;
    H4[(size_t)n * 32 + sub * 2 + 1] = o1;
}

// ---------------- graph mean pool, two-stage ----------------
__global__ void pool_kernel() {
    int g = blockIdx.x;
    int c = blockIdx.y;
    int t = threadIdx.x;
    int b0 = g_gstart[g], b1 = g_gstart[g + 1];
    int len = b1 - b0;
    int chunk = (len + 7) >> 3;
    int lo = b0 + c * chunk;
    int hi = min(lo + chunk, b1);
    float acc = 0.f;
#pragma unroll 4
    for (int n = lo; n < hi; n++) acc += g_H1[(size_t)n * HD + t];
    g_poolp[((size_t)g * 8 + c) * HD + t] = acc;
}

// ---------------- classifier head ----------------
__global__ void classifier_kernel(const float* __restrict__ cW1, const float* __restrict__ cb1,
                                  const float* __restrict__ cW2, const float* __restrict__ cb2,
                                  float* __restrict__ out) {
    __shared__ float gs[HD];
    __shared__ float hid[HD];
    int g = blockIdx.x;
    int t = threadIdx.x;
    float s = 0.f;
#pragma unroll
    for (int c = 0; c < 8; c++) s += g_poolp[((size_t)g * 8 + c) * HD + t];
    float cnt = (float)max(g_gstart[g + 1] - g_gstart[g], 1);
    gs[t] = s / cnt;
    __syncthreads();
    float acc = cb1[t];
#pragma unroll 8
    for (int c = 0; c < HD; c++) acc = fmaf(gs[c], cW1[c * 128 + t], acc);
    hid[t] = fmaxf(acc, 0.f);
    __syncthreads();
    if (t < 30) {
        float o = cb2[t];
#pragma unroll 8
        for (int j = 0; j < HD; j++) o = fmaf(hid[j], cW2[j * 30 + t], o);
        out[g * 30 + t] = o;
    }
}

// ---------------- launch ----------------
extern "C" void kernel_launch(void* const* d_in, const int* in_sizes, int n_in,
                              void* d_out, int out_size) {
    const float* x      = (const float*)d_in[0];
    const int*   ei     = (const int*)d_in[1];
    const float* eattr  = (const float*)d_in[2];
    const int*   batch  = (const int*)d_in[3];
    const float* l0_Wq = (const float*)d_in[4];
    const float* l0_bq = (const float*)d_in[5];
    const float* l0_Wk = (const float*)d_in[6];
    const float* l0_bk = (const float*)d_in[7];
    const float* l0_Wv = (const float*)d_in[8];
    const float* l0_bv = (const float*)d_in[9];
    const float* l0_We = (const float*)d_in[10];
    const float* l0_Ws = (const float*)d_in[11];
    const float* l0_bs = (const float*)d_in[12];
    const float* l1_Wq = (const float*)d_in[13];
    const float* l1_bq = (const float*)d_in[14];
    const float* l1_Wk = (const float*)d_in[15];
    const float* l1_bk = (const float*)d_in[16];
    const float* l1_Wv = (const float*)d_in[17];
    const float* l1_bv = (const float*)d_in[18];
    const float* l1_We = (const float*)d_in[19];
    const float* l1_Ws = (const float*)d_in[20];
    const float* l1_bs = (const float*)d_in[21];
    const float* cW1   = (const float*)d_in[22];
    const float* cb1   = (const float*)d_in[23];
    const float* cW2   = (const float*)d_in[24];
    const float* cb2   = (const float*)d_in[25];
    float* out = (float*)d_out;

    int N = in_sizes[3];       // batch length = #nodes
    int E = in_sizes[2];       // edge_attr length = #edges
    const int* src = ei;
    const int* dst = ei + E;

    // zero degree+cursor with ONE memset node (combined buffer)
    void* dcPtr = nullptr;
    cudaGetSymbolAddress(&dcPtr, g_degcnt);
    cudaMemsetAsync(dcPtr, 0, (size_t)2 * NMAX * sizeof(int));

    // weight pre-split (independent of CSR; tiny)
    prepW_kernel<<<128, 256>>>(l1_Wq, l1_Wk, l1_Wv, l1_Ws);

    // CSR build (reused by both layers)
    hist_kernel<<<(E + 255) / 256, 256>>>(dst, E);
    scan_kernel<<<1, 1024>>>(N);
    scatter_kernel<<<(E + 255) / 256, 256>>>(src, dst, eattr, E);

    // layer 0: algebraically collapsed (in_ch = 2); prep0 also computes gstart
    prep0_kernel<<<1, 1024>>>(l0_Wq, l0_bq, l0_Wk, l0_bk, l0_We,
                              l0_Wv, l0_bv, l0_Ws, l0_bs, batch, N);
    attn0_kernel<<<(N + 127) / 128, 128>>>(x, N);

    // layer 1 projections: fused H0-generation + fp16-split tensor GEMM
    dim3 ggrid((N + 127) / 128, 4);
    gemm3_kernel<<<ggrid, 256>>>(x, N, l1_bq, l1_bk, l1_bv, l1_bs);

    // layer 1 attention: warp per node, 2 edges per iteration
    attn_kernel<<<(N * 32 + 255) / 256, 256>>>(l1_We, N);

    // pool (two-stage) + head
    dim3 pgrid(GMAX, 8);
    pool_kernel<<<pgrid, HD>>>();
    classifier_kernel<<<GMAX, HD>>>(cW1, cb1, cW2, cb2, out);
}

// round 16
// speedup vs baseline: 1.0761x; 1.0761x over previous
#include <cuda_runtime.h>
#include <cuda_fp16.h>
#include <cstdint>

// ---------------- problem constants ----------------
#define NMAX   50048      // padded node capacity
#define EMAX   800000
#define GMAX   64
#define HD     128        // hidden dim (H*D)
#define PW     256        // q|skip packed row width for layer 1

// ---------------- static scratch (no allocs allowed) ----------------
__device__ float    g_P[(size_t)NMAX * PW];    // layer1 packed q|s (fp32)
__device__ __half2  g_KV[(size_t)NMAX * 128];  // layer1 per node: k | v (fp16)
__device__ float    g_H1[(size_t)NMAX * HD];   // layer1 output (post relu)
__device__ float    g_A[(size_t)NMAX * 8];     // layer0 compact attn results
__device__ float    g_M0[18];                  // layer0 3x3 bilinear forms (2 heads)
__device__ float    g_cq0[6];                  // layer0 q.We coefficient 3-vectors
__device__ float    g_C[9 * 128];              // layer0 expansion matrix (Z @ C = H0)
__device__ int      g_degcnt[2 * NMAX];        // [0,NMAX): degree, [NMAX,2N): scatter cursor
__device__ int      g_rowptr[NMAX + 1];
__device__ int2     g_edge[EMAX];              // packed (src, attr-bits)
__device__ int      g_gstart[GMAX + 1];
__device__ float    g_poolp[GMAX * 8 * HD];    // partial pool sums

// ---------------- CSR build ----------------
__global__ void hist_kernel(const int* __restrict__ dst, int E) {
    int i = blockIdx.x * blockDim.x + threadIdx.x;
    if (i < E) atomicAdd(&g_degcnt[dst[i]], 1);
}

__global__ void scan_kernel(int N) {
    __shared__ int sums[1024];
    int t = threadIdx.x;
    int chunk = (N + 1023) >> 10;
    chunk = (chunk + 3) & ~3;
    int lo = t * chunk;
    int hi = min(lo + chunk, N);
    int s = 0;
    int i = lo;
    for (; i + 4 <= hi; i += 4) {
        int4 v = *(const int4*)(g_degcnt + i);
        s += v.x + v.y + v.z + v.w;
    }
    for (; i < hi; i++) s += g_degcnt[i];
    sums[t] = s;
    __syncthreads();
    for (int off = 1; off < 1024; off <<= 1) {
        int v = (t >= off) ? sums[t - off] : 0;
        __syncthreads();
        sums[t] += v;
        __syncthreads();
    }
    int run = sums[t] - s;
    for (int j = lo; j < hi; j++) { g_rowptr[j] = run; run += g_degcnt[j]; }
    if (t == 1023) g_rowptr[N] = sums[1023];
}

__global__ void scatter_kernel(const int* __restrict__ src,
                               const int* __restrict__ dst,
                               const float* __restrict__ attr, int E) {
    int i = blockIdx.x * blockDim.x + threadIdx.x;
    if (i >= E) return;
    int d = dst[i];
    int p = g_rowptr[d] + atomicAdd(&g_degcnt[NMAX + d], 1);
    g_edge[p] = make_int2(src[i], __float_as_int(attr[i]));
}

// ---------------- layer-0 precompute: warp-parallel bilinear forms + C + gstart ----------------
__global__ void prep0_kernel(const float* __restrict__ Wq, const float* __restrict__ bq,
                             const float* __restrict__ Wk, const float* __restrict__ bk,
                             const float* __restrict__ We,
                             const float* __restrict__ Wv, const float* __restrict__ bv,
                             const float* __restrict__ Ws, const float* __restrict__ bs,
                             const int* __restrict__ batch, int N) {
    int tid  = threadIdx.x;
    int w    = tid >> 5, lane = tid & 31;
    if (w < 24) {
        const float* arow; const float* brow;
        if (w < 18) {
            int h = w / 9, rem = w % 9, r = rem / 3, c = rem % 3;
            arow = (r < 2) ? (Wq + r * 128 + h * 64) : (bq + h * 64);
            brow = (c < 2) ? (Wk + c * 128 + h * 64) : (bk + h * 64);
        } else {
            int j = w - 18, h = j / 3, r = j % 3;
            arow = (r < 2) ? (Wq + r * 128 + h * 64) : (bq + h * 64);
            brow = We + h * 64;
        }
        float s = arow[lane] * brow[lane] + arow[lane + 32] * brow[lane + 32];
#pragma unroll
        for (int off = 16; off; off >>= 1) s += __shfl_xor_sync(0xffffffffu, s, off);
        if (lane == 0) {
            if (w < 18) g_M0[w] = s; else g_cq0[w - 18] = s;
        }
    }
    int t2 = tid - 768;
    if (t2 >= 0 && t2 < 128) {
        int h = t2 >> 6;
        g_C[0 * 128 + t2] = (h == 0) ? Wv[t2]        : 0.f;
        g_C[1 * 128 + t2] = (h == 0) ? Wv[128 + t2]  : 0.f;
        g_C[2 * 128 + t2] = (h == 0) ? We[t2]        : 0.f;
        g_C[3 * 128 + t2] = (h == 1) ? Wv[t2]        : 0.f;
        g_C[4 * 128 + t2] = (h == 1) ? Wv[128 + t2]  : 0.f;
        g_C[5 * 128 + t2] = (h == 1) ? We[t2]        : 0.f;
        g_C[6 * 128 + t2] = Ws[t2];
        g_C[7 * 128 + t2] = Ws[128 + t2];
        g_C[8 * 128 + t2] = bv[t2] + bs[t2];
    }
    // graph starts: binary search on sorted batch (threads 896..960)
    int t3 = tid - 896;
    if (t3 >= 0 && t3 <= GMAX) {
        int lo = 0, hi = N;
        while (lo < hi) {
            int mid = (lo + hi) >> 1;
            if (batch[mid] < t3) lo = mid + 1; else hi = mid;
        }
        g_gstart[t3] = lo;
    }
}

// ---------------- layer-0 attention: one THREAD per node ----------------
__global__ void attn0_kernel(const float* __restrict__ x, int N) {
    __shared__ float sM[18], sC[6];
    int t = threadIdx.x;
    if (t < 18) sM[t] = g_M0[t];
    if (t < 6)  sC[t] = g_cq0[t];
    __syncthreads();

    int n = blockIdx.x * blockDim.x + t;
    if (n >= N) return;

    const float2* x2 = (const float2*)x;
    float2 xd = __ldg(x2 + n);

    float w[2][3], cqd[2];
#pragma unroll
    for (int h = 0; h < 2; h++) {
#pragma unroll
        for (int j = 0; j < 3; j++)
            w[h][j] = fmaf(xd.x, sM[h * 9 + j], fmaf(xd.y, sM[h * 9 + 3 + j], sM[h * 9 + 6 + j]));
        cqd[h] = fmaf(xd.x, sC[h * 3], fmaf(xd.y, sC[h * 3 + 1], sC[h * 3 + 2]));
    }

    float m[2]   = {-1e30f, -1e30f};
    float den[2] = {0.f, 0.f};
    float S0[2]  = {0.f, 0.f};
    float S1[2]  = {0.f, 0.f};
    float Sa[2]  = {0.f, 0.f};

    int beg = g_rowptr[n], end = g_rowptr[n + 1];
    float aNxt = 0.f; float2 xsNxt = make_float2(0.f, 0.f);
    if (beg < end) {
        int2 e = __ldg(g_edge + beg);
        aNxt = __int_as_float(e.y);
        xsNxt = __ldg(x2 + e.x);
    }
    for (int i = beg; i < end; i++) {
        float a = aNxt; float2 xs = xsNxt;
        if (i + 1 < end) {
            int2 e = __ldg(g_edge + i + 1);
            aNxt = __int_as_float(e.y);
            xsNxt = __ldg(x2 + e.x);
        }
#pragma unroll
        for (int h = 0; h < 2; h++) {
            float l = fmaf(a, cqd[h],
                      fmaf(xs.x, w[h][0], fmaf(xs.y, w[h][1], w[h][2]))) * 0.125f;
            float nm = fmaxf(m[h], l);
            float sc = __expf(m[h] - nm);
            float ex = __expf(l - nm);
            S0[h] = fmaf(S0[h], sc, ex * xs.x);
            S1[h] = fmaf(S1[h], sc, ex * xs.y);
            Sa[h] = fmaf(Sa[h], sc, ex * a);
            den[h] = fmaf(den[h], sc, ex);
            m[h] = nm;
        }
    }

    float4* A4 = (float4*)g_A;
#pragma unroll
    for (int h = 0; h < 2; h++) {
        float inv = 1.f / (den[h] + 1e-16f);
        A4[(size_t)n * 2 + h] = make_float4(S0[h] * inv, S1[h] * inv, Sa[h] * inv, 0.f);
    }
}

// ---------------- layer-1 projections: fused H0-gen + fp16-split GEMM (R14-proven) ----------------
#define PA 10     // A half2 row stride (8 + 2 pad)
#define PB 9      // B half2 col stride (8 + 1 pad)

__device__ __forceinline__ void split_f16(float x, __half& h, __half& l) {
    h = __float2half_rn(x);
    l = __float2half_rn(x - __half2float(h));
}
__device__ __forceinline__ uint32_t pack2(__half a, __half b) {
    __half2 t = __halves2half2(a, b);
    return *reinterpret_cast<uint32_t*>(&t);
}

__device__ __forceinline__ void mma16(float* c, const uint32_t* a, const uint32_t* b) {
    asm volatile(
        "mma.sync.aligned.m16n8k16.row.col.f32.f16.f16.f32 "
        "{%0,%1,%2,%3}, {%4,%5,%6,%7}, {%8,%9}, {%0,%1,%2,%3};"
        : "+f"(c[0]), "+f"(c[1]), "+f"(c[2]), "+f"(c[3])
        : "r"(a[0]), "r"(a[1]), "r"(a[2]), "r"(a[3]), "r"(b[0]), "r"(b[1]));
}

__global__ __launch_bounds__(256, 2) void gemm3_kernel(
    const float* __restrict__ x, int N,
    const float* __restrict__ Wq, const float* __restrict__ Wk,
    const float* __restrict__ Wv, const float* __restrict__ Ws,
    const float* __restrict__ bq, const float* __restrict__ bk,
    const float* __restrict__ bv, const float* __restrict__ bs) {
    __shared__ uint32_t AsH[128 * PA];
    __shared__ uint32_t AsL[128 * PA];
    __shared__ uint32_t BsH[128 * PB];
    __shared__ uint32_t BsL[128 * PB];
    __shared__ float Cs[9 * 128];    // expansion matrix
    __shared__ float Zs[128 * 10];   // per-row compact features (8 used, pad 10)

    const float* W; const float* bias;
    int sec = blockIdx.y;
    if (sec == 0)      { W = Wq; bias = bq; }
    else if (sec == 1) { W = Wk; bias = bk; }
    else if (sec == 2) { W = Wv; bias = bv; }
    else               { W = Ws; bias = bs; }
    bool threePass = (sec == 0 || sec == 3);

    int tid  = threadIdx.x;
    int warp = tid >> 5, lane = tid & 31;
    int g    = lane >> 2, tig = lane & 3;
    int wm   = warp >> 2, wn = warp & 3;         // 2 x 4 warp grid
    int blockM = blockIdx.x * 128;

    // load C + Z once
    for (int i = tid; i < 9 * 128; i += 256) Cs[i] = g_C[i];
    if (tid < 128) {
        int r = blockM + tid;
        float4 A0 = make_float4(0.f, 0.f, 0.f, 0.f);
        float4 A1 = A0;
        float2 xn = make_float2(0.f, 0.f);
        if (r < N) {
            const float4* A4 = (const float4*)g_A;
            A0 = A4[(size_t)r * 2];
            A1 = A4[(size_t)r * 2 + 1];
            xn = ((const float2*)x)[r];
        }
        float* z = &Zs[tid * 10];
        z[0] = A0.x; z[1] = A0.y; z[2] = A0.z;
        z[3] = A1.x; z[4] = A1.y; z[5] = A1.z;
        z[6] = xn.x; z[7] = xn.y;
    }

    float acc[4][4][4];
#pragma unroll
    for (int mt = 0; mt < 4; mt++)
#pragma unroll
        for (int nt = 0; nt < 4; nt++)
#pragma unroll
            for (int c = 0; c < 4; c++) acc[mt][nt][c] = 0.f;

    int bkp = tid >> 5;          // B loader: k-pair 0..7
    int bc4 = tid & 31;          // B loader: col group (4 cols)

#pragma unroll 1
    for (int kp8 = 0; kp8 < 8; kp8++) {
        int k0 = kp8 * 16;
        __syncthreads();
        // A panel: compute H0[128, k0:k0+16] = relu(Z @ C) on the fly
#pragma unroll
        for (int j = 0; j < 2; j++) {
            int pos = tid + 256 * j;
            int row = pos >> 2;
            int c4  = pos & 3;
            const float* zr = &Zs[row * 10];
            float vals[4];
#pragma unroll
            for (int e = 0; e < 4; e++) {
                int col = k0 + c4 * 4 + e;
                float a = Cs[8 * 128 + col];
#pragma unroll
                for (int i2 = 0; i2 < 8; i2++) a = fmaf(zr[i2], Cs[i2 * 128 + col], a);
                vals[e] = fmaxf(a, 0.f);
            }
            __half hx, lx, hy, ly, hz, lz, hw, lw;
            split_f16(vals[0], hx, lx); split_f16(vals[1], hy, ly);
            split_f16(vals[2], hz, lz); split_f16(vals[3], hw, lw);
            AsH[row * PA + c4 * 2]     = pack2(hx, hy);
            AsH[row * PA + c4 * 2 + 1] = pack2(hz, hw);
            AsL[row * PA + c4 * 2]     = pack2(lx, ly);
            AsL[row * PA + c4 * 2 + 1] = pack2(lz, lw);
        }
        // B panel: 16 k x 128 cols -> col-major half2 k-pairs
        {
            const float* wp = W + (size_t)(k0 + 2 * bkp) * 128 + bc4 * 4;
            float4 r0 = *(const float4*)wp;
            float4 r1 = *(const float4*)(wp + 128);
            const float* f0 = &r0.x;
            const float* f1 = &r1.x;
#pragma unroll
            for (int j = 0; j < 4; j++) {
                __half h0, l0, h1, l1;
                split_f16(f0[j], h0, l0);
                split_f16(f1[j], h1, l1);
                int col = bc4 * 4 + j;
                BsH[col * PB + bkp] = pack2(h0, h1);
                BsL[col * PB + bkp] = pack2(l0, l1);
            }
        }
        __syncthreads();

        uint32_t bh[4][2], bl[4][2];
#pragma unroll
        for (int nt = 0; nt < 4; nt++) {
            int col = wn * 32 + nt * 8 + g;
            bh[nt][0] = BsH[col * PB + tig];
            bh[nt][1] = BsH[col * PB + tig + 4];
            bl[nt][0] = BsL[col * PB + tig];
            bl[nt][1] = BsL[col * PB + tig + 4];
        }
#pragma unroll
        for (int mt = 0; mt < 4; mt++) {
            int r0 = wm * 64 + mt * 16 + g;
            uint32_t ah[4], al[4];
            ah[0] = AsH[r0 * PA + tig];
            ah[1] = AsH[(r0 + 8) * PA + tig];
            ah[2] = AsH[r0 * PA + tig + 4];
            ah[3] = AsH[(r0 + 8) * PA + tig + 4];
            al[0] = AsL[r0 * PA + tig];
            al[1] = AsL[(r0 + 8) * PA + tig];
            al[2] = AsL[r0 * PA + tig + 4];
            al[3] = AsL[(r0 + 8) * PA + tig + 4];
#pragma unroll
            for (int nt = 0; nt < 4; nt++) {
                mma16(acc[mt][nt], ah, bh[nt]);                  // hi*hi
                mma16(acc[mt][nt], ah, bl[nt]);                  // hi*lo
                if (threePass) mma16(acc[mt][nt], al, bh[nt]);   // lo*hi (q/skip only)
            }
        }
    }

    // epilogue: q -> P cols 0..127; s -> P cols 128..255; k/v -> fp16 KV only
    bool isKV = (sec == 1 || sec == 2);
    int kvOff = (sec == 2) ? 64 : 0;
    int pOff  = (sec == 3) ? 128 : 0;
#pragma unroll
    for (int mt = 0; mt < 4; mt++) {
        int r0 = blockM + wm * 64 + mt * 16 + g;
#pragma unroll
        for (int nt = 0; nt < 4; nt++) {
            int cn = wn * 32 + nt * 8 + tig * 2;
            float b0 = bias[cn], b1 = bias[cn + 1];
            float2 v0 = make_float2(acc[mt][nt][0] + b0, acc[mt][nt][1] + b1);
            float2 v1 = make_float2(acc[mt][nt][2] + b0, acc[mt][nt][3] + b1);
            if (isKV) {
                g_KV[(size_t)r0 * 128 + kvOff + cn / 2]       = __floats2half2_rn(v0.x, v0.y);
                g_KV[(size_t)(r0 + 8) * 128 + kvOff + cn / 2] = __floats2half2_rn(v1.x, v1.y);
            } else {
                *(float2*)(g_P + (size_t)r0 * PW + pOff + cn)       = v0;
                *(float2*)(g_P + (size_t)(r0 + 8) * PW + pOff + cn) = v1;
            }
        }
    }
}

// ---------------- layer-1 edge attention: warp = 1 node, 2 edges/iter ----------------
__device__ __forceinline__ void cvt8(uint4 r, float4& lo, float4& hi) {
    __half2 h0 = *reinterpret_cast<__half2*>(&r.x);
    __half2 h1 = *reinterpret_cast<__half2*>(&r.y);
    __half2 h2 = *reinterpret_cast<__half2*>(&r.z);
    __half2 h3 = *reinterpret_cast<__half2*>(&r.w);
    float2 a = __half22float2(h0), b = __half22float2(h1);
    float2 c = __half22float2(h2), d = __half22float2(h3);
    lo = make_float4(a.x, a.y, b.x, b.y);
    hi = make_float4(c.x, c.y, d.x, d.y);
}

__device__ __forceinline__ float dot8v(float4 a0, float4 a1, float4 b0, float4 b1) {
    return a0.x * b0.x + a0.y * b0.y + a0.z * b0.z + a0.w * b0.w
         + a1.x * b1.x + a1.y * b1.y + a1.z * b1.z + a1.w * b1.w;
}

__global__ void attn_kernel(const float* __restrict__ We, int N) {
    int gt   = blockIdx.x * blockDim.x + threadIdx.x;
    int lane = threadIdx.x & 31;
    int eh   = lane >> 4;          // which edge of the pair this half-warp handles
    int sub  = lane & 15;          // dims sub*8 .. sub*8+7
    int n    = gt >> 5;
    if (n >= N) return;

    const float4* P4 = (const float4*)g_P;
    size_t base = (size_t)n * 64;
    float4 q0 = __ldg(P4 + base + sub * 2);
    float4 q1 = __ldg(P4 + base + sub * 2 + 1);
    float4 w0 = __ldg((const float4*)We + sub * 2);
    float4 w1 = __ldg((const float4*)We + sub * 2 + 1);

    float qWe = dot8v(q0, q1, w0, w1);
    qWe += __shfl_xor_sync(0xffffffffu, qWe, 4);
    qWe += __shfl_xor_sync(0xffffffffu, qWe, 2);
    qWe += __shfl_xor_sync(0xffffffffu, qWe, 1);

    int beg = g_rowptr[n], end = g_rowptr[n + 1];
    int deg = end - beg;
    int npair = (deg + 1) >> 1;

    float4 acc0 = make_float4(0.f, 0.f, 0.f, 0.f);
    float4 acc1 = make_float4(0.f, 0.f, 0.f, 0.f);
    float m = -1e30f, den = 0.f, sa = 0.f;

    for (int i = 0; i < npair; i++) {
        int idx = beg + 2 * i + eh;
        bool v = (idx < end);
        int2 e = __ldg(g_edge + (v ? idx : beg));
        float a = __int_as_float(e.y);
        const uint4* b4 = (const uint4*)(g_KV + (size_t)e.x * 128);
        uint4 kr = __ldg(b4 + sub);
        uint4 vr = __ldg(b4 + 16 + sub);

        float4 k0, k1; cvt8(kr, k0, k1);
        float part = dot8v(q0, q1, k0, k1);
        part += __shfl_xor_sync(0xffffffffu, part, 4);
        part += __shfl_xor_sync(0xffffffffu, part, 2);
        part += __shfl_xor_sync(0xffffffffu, part, 1);
        float l = (part + a * qWe) * 0.125f;

        float nm = v ? fmaxf(m, l) : m;
        float sc = __expf(m - nm);
        float ex = v ? __expf(l - nm) : 0.f;

        float4 v0, v1; cvt8(vr, v0, v1);
        acc0.x = fmaf(acc0.x, sc, ex * v0.x);
        acc0.y = fmaf(acc0.y, sc, ex * v0.y);
        acc0.z = fmaf(acc0.z, sc, ex * v0.z);
        acc0.w = fmaf(acc0.w, sc, ex * v0.w);
        acc1.x = fmaf(acc1.x, sc, ex * v1.x);
        acc1.y = fmaf(acc1.y, sc, ex * v1.y);
        acc1.z = fmaf(acc1.z, sc, ex * v1.z);
        acc1.w = fmaf(acc1.w, sc, ex * v1.w);
        den = fmaf(den, sc, ex);
        sa  = fmaf(sa,  sc, ex * a);
        m = nm;
    }

    // exact merge of the two half-warp states
    float mO = __shfl_xor_sync(0xffffffffu, m, 16);
    float nm = fmaxf(m, mO);
    float eS = __expf(m - nm);
    den *= eS; sa *= eS;
    acc0.x *= eS; acc0.y *= eS; acc0.z *= eS; acc0.w *= eS;
    acc1.x *= eS; acc1.y *= eS; acc1.z *= eS; acc1.w *= eS;
    den += __shfl_xor_sync(0xffffffffu, den, 16);
    sa  += __shfl_xor_sync(0xffffffffu, sa, 16);
    acc0.x += __shfl_xor_sync(0xffffffffu, acc0.x, 16);
    acc0.y += __shfl_xor_sync(0xffffffffu, acc0.y, 16);
    acc0.z += __shfl_xor_sync(0xffffffffu, acc0.z, 16);
    acc0.w += __shfl_xor_sync(0xffffffffu, acc0.w, 16);
    acc1.x += __shfl_xor_sync(0xffffffffu, acc1.x, 16);
    acc1.y += __shfl_xor_sync(0xffffffffu, acc1.y, 16);
    acc1.z += __shfl_xor_sync(0xffffffffu, acc1.z, 16);
    acc1.w += __shfl_xor_sync(0xffffffffu, acc1.w, 16);

    acc0.x = fmaf(sa, w0.x, acc0.x);
    acc0.y = fmaf(sa, w0.y, acc0.y);
    acc0.z = fmaf(sa, w0.z, acc0.z);
    acc0.w = fmaf(sa, w0.w, acc0.w);
    acc1.x = fmaf(sa, w1.x, acc1.x);
    acc1.y = fmaf(sa, w1.y, acc1.y);
    acc1.z = fmaf(sa, w1.z, acc1.z);
    acc1.w = fmaf(sa, w1.w, acc1.w);

    if (eh) return;   // lower half-warp stores the full row
    float inv = 1.f / (den + 1e-16f);
    float4 s0 = __ldg(P4 + base + 32 + sub * 2);
    float4 s1 = __ldg(P4 + base + 32 + sub * 2 + 1);
    float4 o0, o1;
    o0.x = fmaxf(fmaf(acc0.x, inv, s0.x), 0.f);
    o0.y = fmaxf(fmaf(acc0.y, inv, s0.y), 0.f);
    o0.z = fmaxf(fmaf(acc0.z, inv, s0.z), 0.f);
    o0.w = fmaxf(fmaf(acc0.w, inv, s0.w), 0.f);
    o1.x = fmaxf(fmaf(acc1.x, inv, s1.x), 0.f);
    o1.y = fmaxf(fmaf(acc1.y, inv, s1.y), 0.f);
    o1.z = fmaxf(fmaf(acc1.z, inv, s1.z), 0.f);
    o1.w = fmaxf(fmaf(acc1.w, inv, s1.w), 0.f);
    float4* H4 = (float4*)g_H1;
    H4[(size_t)n * 32 + sub * 2]     = o0;
    H4[(size_t)n * 32 + sub * 2 + 1] = o1;
}

// ---------------- graph mean pool, two-stage ----------------
__global__ void pool_kernel() {
    int g = blockIdx.x;
    int c = blockIdx.y;
    int t = threadIdx.x;
    int b0 = g_gstart[g], b1 = g_gstart[g + 1];
    int len = b1 - b0;
    int chunk = (len + 7) >> 3;
    int lo = b0 + c * chunk;
    int hi = min(lo + chunk, b1);
    float acc = 0.f;
#pragma unroll 4
    for (int n = lo; n < hi; n++) acc += g_H1[(size_t)n * HD + t];
    g_poolp[((size_t)g * 8 + c) * HD + t] = acc;
}

// ---------------- classifier head ----------------
__global__ void classifier_kernel(const float* __restrict__ cW1, const float* __restrict__ cb1,
                                  const float* __restrict__ cW2, const float* __restrict__ cb2,
                                  float* __restrict__ out) {
    __shared__ float gs[HD];
    __shared__ float hid[HD];
    int g = blockIdx.x;
    int t = threadIdx.x;
    float s = 0.f;
#pragma unroll
    for (int c = 0; c < 8; c++) s += g_poolp[((size_t)g * 8 + c) * HD + t];
    float cnt = (float)max(g_gstart[g + 1] - g_gstart[g], 1);
    gs[t] = s / cnt;
    __syncthreads();
    float acc = cb1[t];
#pragma unroll 8
    for (int c = 0; c < HD; c++) acc = fmaf(gs[c], cW1[c * 128 + t], acc);
    hid[t] = fmaxf(acc, 0.f);
    __syncthreads();
    if (t < 30) {
        float o = cb2[t];
#pragma unroll 8
        for (int j = 0; j < HD; j++) o = fmaf(hid[j], cW2[j * 30 + t], o);
        out[g * 30 + t] = o;
    }
}

// ---------------- launch ----------------
extern "C" void kernel_launch(void* const* d_in, const int* in_sizes, int n_in,
                              void* d_out, int out_size) {
    const float* x      = (const float*)d_in[0];
    const int*   ei     = (const int*)d_in[1];
    const float* eattr  = (const float*)d_in[2];
    const int*   batch  = (const int*)d_in[3];
    const float* l0_Wq = (const float*)d_in[4];
    const float* l0_bq = (const float*)d_in[5];
    const float* l0_Wk = (const float*)d_in[6];
    const float* l0_bk = (const float*)d_in[7];
    const float* l0_Wv = (const float*)d_in[8];
    const float* l0_bv = (const float*)d_in[9];
    const float* l0_We = (const float*)d_in[10];
    const float* l0_Ws = (const float*)d_in[11];
    const float* l0_bs = (const float*)d_in[12];
    const float* l1_Wq = (const float*)d_in[13];
    const float* l1_bq = (const float*)d_in[14];
    const float* l1_Wk = (const float*)d_in[15];
    const float* l1_bk = (const float*)d_in[16];
    const float* l1_Wv = (const float*)d_in[17];
    const float* l1_bv = (const float*)d_in[18];
    const float* l1_We = (const float*)d_in[19];
    const float* l1_Ws = (const float*)d_in[20];
    const float* l1_bs = (const float*)d_in[21];
    const float* cW1   = (const float*)d_in[22];
    const float* cb1   = (const float*)d_in[23];
    const float* cW2   = (const float*)d_in[24];
    const float* cb2   = (const float*)d_in[25];
    float* out = (float*)d_out;

    int N = in_sizes[3];       // batch length = #nodes
    int E = in_sizes[2];       // edge_attr length = #edges
    const int* src = ei;
    const int* dst = ei + E;

    // zero degree+cursor with ONE memset node (combined buffer)
    void* dcPtr = nullptr;
    cudaGetSymbolAddress(&dcPtr, g_degcnt);
    cudaMemsetAsync(dcPtr, 0, (size_t)2 * NMAX * sizeof(int));

    // CSR build (reused by both layers)
    hist_kernel<<<(E + 255) / 256, 256>>>(dst, E);
    scan_kernel<<<1, 1024>>>(N);
    scatter_kernel<<<(E + 255) / 256, 256>>>(src, dst, eattr, E);

    // layer 0: algebraically collapsed (in_ch = 2); prep0 also computes gstart
    prep0_kernel<<<1, 1024>>>(l0_Wq, l0_bq, l0_Wk, l0_bk, l0_We,
                              l0_Wv, l0_bv, l0_Ws, l0_bs, batch, N);
    attn0_kernel<<<(N + 127) / 128, 128>>>(x, N);

    // layer 1 projections: fused H0-generation + fp16-split tensor GEMM (R14 config)
    dim3 ggrid((N + 127) / 128, 4);
    gemm3_kernel<<<ggrid, 256>>>(x, N, l1_Wq, l1_Wk, l1_Wv, l1_Ws,
                                 l1_bq, l1_bk, l1_bv, l1_bs);

    // layer 1 attention: warp per node, 2 edges per iteration
    attn_kernel<<<(N * 32 + 255) / 256, 256>>>(l1_We, N);

    // pool (two-stage) + head
    dim3 pgrid(GMAX, 8);
    pool_kernel<<<pgrid, HD>>>();
    classifier_kernel<<<GMAX, HD>>>(cW1, cb1, cW2, cb2, out);
}